// round 11
// baseline (speedup 1.0000x reference)
#include <cuda_runtime.h>
#include <cuda_bf16.h>

// Problem geometry
#define BATCH   8
#define HIN     1024
#define WIN     1024
#define HC      1025                 // code-grid rows
#define WC      1025                 // code-grid cols
#define CELLS   (HC * WC)            // 1,050,625 cells per batch
#define WCP     1028                 // padded code-row stride (mult of 4)
#define CSTRIDE (HC * WCP)           // per-batch code stride
#define RPB1    8                    // rows per phase-1 chunk
#define NBB1    129                  // chunks per batch
#define NCHUNK  (BATCH * NBB1)       // 1032 phase-1 chunks
#define TPB     256
#define NBLK    592                  // 4 CTAs/SM x 148 SMs — guaranteed co-resident
#define NWARPS  (NBLK * 8)           // 4736 phase-2 warps
#define GROWS   (BATCH * HC)         // 8200 global rows
#define NROWS   (2 * BATCH * CELLS)  // 16,810,000 output rows (float4 each)
#define ZSTART  (BATCH * CELLS)      // 8,405,000 = E[total]

// -------- scratch (static device globals; no allocation allowed) ----------
__device__ unsigned char g_codes[(size_t)BATCH * CSTRIDE];
__device__ unsigned int  g_cnt1[GROWS];
__device__ unsigned int  g_cnt2[GROWS];
__device__ unsigned int  g_off1[GROWS];
__device__ unsigned int  g_off2[GROWS];
__device__ unsigned int  g_total;
__device__ unsigned int  g_arrive;   // 0 -> NBLK -> 2*NBLK -> reset 0
__device__ unsigned int  g_depart;   // reset bookkeeping

// Midpoint offsets per code (FIRST table): row = [y+f.x, x+f.y, y+f.z, x+f.w]
__constant__ float4 c_F[16] = {
    { 0.0f,  0.0f,  0.0f,  0.0f},  // 0  (invalid)
    { 0.0f, -0.5f,  0.5f,  0.0f},  // 1
    { 0.5f,  0.0f,  0.0f,  0.5f},  // 2
    { 0.0f, -0.5f,  0.0f,  0.5f},  // 3
    { 0.0f,  0.5f, -0.5f,  0.0f},  // 4
    { 0.0f, -0.5f,  0.5f,  0.0f},  // 5
    { 0.5f,  0.0f, -0.5f,  0.0f},  // 6
    { 0.0f, -0.5f, -0.5f,  0.0f},  // 7
    {-0.5f,  0.0f,  0.0f, -0.5f},  // 8
    {-0.5f,  0.0f,  0.5f,  0.0f},  // 9
    { 0.5f,  0.0f,  0.0f,  0.5f},  // 10
    {-0.5f,  0.0f,  0.0f,  0.5f},  // 11
    { 0.0f,  0.5f,  0.0f, -0.5f},  // 12
    { 0.0f,  0.5f,  0.5f,  0.0f},  // 13
    { 0.5f,  0.0f,  0.0f, -0.5f},  // 14
    { 0.0f,  0.0f,  0.0f,  0.0f},  // 15 (invalid)
};
// SECOND[5] = (0, 0.5, -0.5, 0), SECOND[10] = (-0.5, 0, 0, -0.5) inlined.

__global__ __launch_bounds__(TPB, 4)
void ms_fused(const float* __restrict__ in, float* __restrict__ out, int out_size)
{
    float4* __restrict__ out4 = (float4*)out;
    const int bk   = blockIdx.x;
    const int t    = threadIdx.x;
    const int lane = t & 31;
    const int wid  = t >> 5;

    __shared__ unsigned r1s[RPB1][8], r2s[RPB1][8];

    // ================= Phase 1: codes + per-row counts =====================
    for (int cidx = bk; cidx < NCHUNK; cidx += NBLK) {
        const int b     = cidx / NBB1;
        const int chunk = cidx - b * NBB1;
        const int y0    = chunk * RPB1;
        const int yend  = min(y0 + RPB1, HC);
        const float* __restrict__ img = in + (size_t)b * HIN * WIN;
        unsigned char* __restrict__ crow0 = g_codes + (size_t)b * CSTRIDE;
        const int col = 4 * t;

        const float* rA = img + (size_t)max(min(y0 - 1, HIN - 1), 0) * WIN;
        float4 vA = *(const float4*)(rA + col);
        float lmA = __shfl_up_sync(0xffffffffu, vA.w, 1);
        if (lane == 0) lmA = (col > 0) ? rA[col - 1] : vA.x;

        for (int y = y0; y < yend; y++) {
            const float* rB = img + (size_t)min(y, HIN - 1) * WIN;
            float4 vB = *(const float4*)(rB + col);
            float lmB = __shfl_up_sync(0xffffffffu, vB.w, 1);
            if (lane == 0) lmB = (col > 0) ? rB[col - 1] : vB.x;

            const float la[4] = {lmA, vA.x, vA.y, vA.z};
            const float ra[4] = {vA.x, vA.y, vA.z, vA.w};
            const float lb[4] = {lmB, vB.x, vB.y, vB.z};
            const float rb[4] = {vB.x, vB.y, vB.z, vB.w};

            unsigned packed = 0, c1 = 0, c2 = 0;
            #pragma unroll
            for (int j = 0; j < 4; j++) {
                unsigned code = (lb[j] > 0.0f ? 1u : 0u) | (rb[j] > 0.0f ? 2u : 0u) |
                                (ra[j] > 0.0f ? 4u : 0u) | (la[j] > 0.0f ? 8u : 0u);
                packed |= code << (8 * j);
                c1 += (code - 1u) < 14u;
                c2 += (code == 5u) | (code == 10u);
            }
            unsigned char* crow = crow0 + (size_t)y * WCP;
            *(unsigned int*)(crow + col) = packed;
            if (t == TPB - 1) {              // cell x = 1024 (clamped both sides)
                unsigned code = (vB.w > 0.0f ? 3u : 0u) | (vA.w > 0.0f ? 12u : 0u);
                crow[1024] = (unsigned char)code;
                c1 += (code - 1u) < 14u;     // codes {0,3,12,15}: never table-2
            }
            const unsigned s1 = __reduce_add_sync(0xffffffffu, c1);
            const unsigned s2 = __reduce_add_sync(0xffffffffu, c2);
            if (lane == 0) { r1s[y - y0][wid] = s1; r2s[y - y0][wid] = s2; }
            vA = vB; lmA = lmB;              // row reuse: bottom(y) == top(y+1)
        }
        __syncthreads();
        if (t < yend - y0) {
            unsigned t1 = 0, t2 = 0;
            #pragma unroll
            for (int w = 0; w < 8; w++) { t1 += r1s[t][w]; t2 += r2s[t][w]; }
            g_cnt1[b * HC + y0 + t] = t1;
            g_cnt2[b * HC + y0 + t] = t2;
        }
        __syncthreads();
    }

    // speculative zero of [ZSTART, NROWS) — overlaps other blocks' phase 1
    {
        const unsigned zn = (unsigned)(NROWS - ZSTART);
        const unsigned cz = (zn + NBLK - 1) / NBLK;
        const unsigned s  = (unsigned)ZSTART + (unsigned)bk * cz;
        const unsigned e  = min(s + cz, (unsigned)NROWS);
        const float4 z = make_float4(0.0f, 0.0f, 0.0f, 0.0f);
        for (unsigned i = s + t; i < e; i += TPB) __stwt(&out4[i], z);
    }

    // ================= grid barrier + inline scan ==========================
    __shared__ unsigned slast;
    if (t == 0) {
        __threadfence();                     // publish codes + counts + zeros
        const unsigned old = atomicAdd(&g_arrive, 1u);
        slast = (old == (unsigned)(NBLK - 1)) ? 1u : 0u;
    }
    __syncthreads();

    if (slast) {                             // uniform across the block
        __threadfence();                     // acquire all g_cnt writes
        __shared__ unsigned tot[16], gbs[17];

        // Sweep A: ALL 16 group totals first (warp wid owns groups 2w, 2w+1)
        #pragma unroll
        for (int rep = 0; rep < 2; rep++) {
            const int g = wid * 2 + rep;
            const unsigned* __restrict__ cnt = (g & 1) ? g_cnt2 : g_cnt1;
            const int base = (g >> 1) * HC;
            unsigned s = 0;
            for (int i = lane; i < HC; i += 32) s += cnt[base + i];
            s = __reduce_add_sync(0xffffffffu, s);
            if (lane == 0) tot[g] = s;
        }
        __syncthreads();                     // ALL tot[] valid now
        if (t == 0) {
            unsigned acc = 0;
            #pragma unroll
            for (int q = 0; q < 16; q++) { gbs[q] = acc; acc += tot[q]; }
            gbs[16] = acc;
            g_total = acc;
        }
        __syncthreads();

        // Sweep B: exclusive offsets per group (reload counts; L2-hot)
        #pragma unroll
        for (int rep = 0; rep < 2; rep++) {
            const int g = wid * 2 + rep;
            const unsigned* __restrict__ cnt = (g & 1) ? g_cnt2 : g_cnt1;
            unsigned*       __restrict__ off = (g & 1) ? g_off2 : g_off1;
            const int base = (g >> 1) * HC;
            unsigned carry = gbs[g];
            for (int i0 = 0; i0 < HC; i0 += 32) {
                const int i = i0 + lane;
                const unsigned v = (i < HC) ? cnt[base + i] : 0u;
                unsigned incl = v;
                #pragma unroll
                for (int o = 1; o < 32; o <<= 1) {
                    const unsigned u = __shfl_up_sync(0xffffffffu, incl, o);
                    if (lane >= o) incl += u;
                }
                if (i < HC) off[base + i] = carry + incl - v;
                carry += __shfl_sync(0xffffffffu, incl, 31);
            }
        }
        __syncthreads();
        if (t < BATCH && out_size >= NROWS * 4 + BATCH)
            out[(size_t)NROWS * 4 + t] = (float)(tot[2 * t] + tot[2 * t + 1]);
        __syncthreads();
        if (t == 0) {
            __threadfence();                 // publish offsets + g_total
            atomicExch(&g_arrive, 2u * NBLK);
        }
    }

    if (t == 0) {
        if (!slast) {
            volatile unsigned* p = &g_arrive;
            while (*p < 2u * NBLK) __nanosleep(128);
        }
        __threadfence();                     // acquire offsets
        const unsigned old = atomicAdd(&g_depart, 1u);
        if (old == (unsigned)(NBLK - 1)) {   // last departer resets for replay
            atomicExch(&g_arrive, 0u);
            atomicExch(&g_depart, 0u);
        }
    }
    __syncthreads();

    // ================= Phase 2: warp-per-row ballot compaction =============
    const unsigned lanelt = (1u << lane) - 1u;
    const int gw = bk * 8 + wid;
    for (int row = gw; row < GROWS; row += NWARPS) {
        const int b = row / HC;
        const int y = row - b * HC;
        const unsigned char* __restrict__ crow =
            g_codes + (size_t)b * CSTRIDE + (size_t)y * WCP;
        unsigned o1 = g_off1[row];
        unsigned o2 = g_off2[row];
        const float fy = (float)y;
        #pragma unroll 3
        for (int i = 0; i < 33; i++) {
            const int x = i * 32 + lane;
            const unsigned code = (x < WC) ? (unsigned)crow[x] : 0u;
            const bool v1 = (code - 1u) < 14u;
            const bool v2 = (code == 5u) | (code == 10u);
            const unsigned m1 = __ballot_sync(0xffffffffu, v1);
            const unsigned m2 = __ballot_sync(0xffffffffu, v2);
            const float cx = (float)x;
            if (v1) {
                const float4 f = c_F[code];
                __stwt(&out4[o1 + __popc(m1 & lanelt)],
                       make_float4(fy + f.x, cx + f.y, fy + f.z, cx + f.w));
            }
            if (v2) {
                const float4 w = (code == 5u)
                    ? make_float4(fy, cx + 0.5f, fy - 0.5f, cx)
                    : make_float4(fy - 0.5f, cx, fy, cx - 0.5f);
                __stwt(&out4[o2 + __popc(m2 & lanelt)], w);
            }
            o1 += __popc(m1);
            o2 += __popc(m2);
        }
    }

    // residual zero: [g_total, ZSTART) when total < ZSTART
    const unsigned total = g_total;
    if (total < (unsigned)ZSTART) {
        const unsigned tail = (unsigned)ZSTART - total;
        const unsigned cz   = (tail + NBLK - 1) / NBLK;
        const unsigned s    = total + (unsigned)bk * cz;
        const unsigned e    = min(s + cz, (unsigned)ZSTART);
        const float4 z = make_float4(0.0f, 0.0f, 0.0f, 0.0f);
        for (unsigned i = s + t; i < e; i += TPB) __stwt(&out4[i], z);
    }
}

// ---------------------------------------------------------------------------
extern "C" void kernel_launch(void* const* d_in, const int* in_sizes, int n_in,
                              void* d_out, int out_size)
{
    const float* coarse = (const float*)d_in[0];
    float* out = (float*)d_out;
    ms_fused<<<NBLK, TPB>>>(coarse, out, out_size);
}